// round 2
// baseline (speedup 1.0000x reference)
#include <cuda_runtime.h>
#include <cstdint>
#include <cstddef>

#define BB 8
#define MM 256
#define CC 128
#define QK_SCALE 0.08838834764831843f  // 1/sqrt(128)

// scratch for q (pre-scaled), k, v : 1 MB each
__device__ float g_q[BB * MM * CC];
__device__ float g_k[BB * MM * CC];
__device__ float g_v[BB * MM * CC];

__device__ __forceinline__ unsigned f2tf(float x) {
    unsigned r;
    asm("cvt.rna.tf32.f32 %0, %1;" : "=r"(r) : "f"(x));
    return r;
}
__device__ __forceinline__ float f2tf_f(float x) { return __uint_as_float(f2tf(x)); }

__device__ __forceinline__ void mma_tf32(float c[4], unsigned a0, unsigned a1,
                                         unsigned a2, unsigned a3,
                                         unsigned b0, unsigned b1) {
    asm volatile(
        "mma.sync.aligned.m16n8k8.row.col.f32.tf32.tf32.f32 "
        "{%0,%1,%2,%3},{%4,%5,%6,%7},{%8,%9},{%0,%1,%2,%3};"
        : "+f"(c[0]), "+f"(c[1]), "+f"(c[2]), "+f"(c[3])
        : "r"(a0), "r"(a1), "r"(a2), "r"(a3), "r"(b0), "r"(b1));
}

// ---------------------------------------------------------------------------
// q/k/v pre-kernel: 256 blocks x 128 threads, 8 rows per block.
// q is pre-scaled by 1/sqrt(C).
// ---------------------------------------------------------------------------
__global__ __launch_bounds__(128) void qkv_kernel(
    const float* __restrict__ annot, const float* __restrict__ prot,
    const float* __restrict__ Wq, const float* __restrict__ bq,
    const float* __restrict__ Wk, const float* __restrict__ bk,
    const float* __restrict__ Wv, const float* __restrict__ bv) {
    __shared__ float sa[8][CC];
    __shared__ float sp[8][CC];
    const int r0 = blockIdx.x * 8;
    const int t = threadIdx.x;

#pragma unroll
    for (int rr = 0; rr < 8; rr++) {
        sa[rr][t] = annot[(r0 + rr) * CC + t];
        sp[rr][t] = prot[(r0 + rr) * CC + t];
    }
    __syncthreads();

    float aq[8], ak[8], av[8];
#pragma unroll
    for (int rr = 0; rr < 8; rr++) { aq[rr] = 0.f; ak[rr] = 0.f; av[rr] = 0.f; }

    const float4* wq4 = reinterpret_cast<const float4*>(Wq + t * CC);
    const float4* wk4 = reinterpret_cast<const float4*>(Wk + t * CC);
    const float4* wv4 = reinterpret_cast<const float4*>(Wv + t * CC);

#pragma unroll 8
    for (int j4 = 0; j4 < 32; j4++) {
        const float4 wq = __ldg(wq4 + j4);
        const float4 wk = __ldg(wk4 + j4);
        const float4 wv = __ldg(wv4 + j4);
#pragma unroll
        for (int rr = 0; rr < 8; rr++) {
            const float4 xa = *reinterpret_cast<const float4*>(&sa[rr][j4 * 4]);
            const float4 xp = *reinterpret_cast<const float4*>(&sp[rr][j4 * 4]);
            aq[rr] += xa.x * wq.x + xa.y * wq.y + xa.z * wq.z + xa.w * wq.w;
            ak[rr] += xp.x * wk.x + xp.y * wk.y + xp.z * wk.z + xp.w * wk.w;
            av[rr] += xa.x * wv.x + xa.y * wv.y + xa.z * wv.z + xa.w * wv.w;
        }
    }

    const float bqv = __ldg(bq + t), bkv = __ldg(bk + t), bvv = __ldg(bv + t);
#pragma unroll
    for (int rr = 0; rr < 8; rr++) {
        const int o = (r0 + rr) * CC + t;
        g_q[o] = (aq[rr] + bqv) * QK_SCALE;
        g_k[o] = ak[rr] + bkv;
        g_v[o] = av[rr] + bvv;
    }
}

// ---------------------------------------------------------------------------
// Fused main kernel: one CTA per (b, m).
//   Phase A: E = mol_adj[b,m] @ Wa^T + ba ; attn = E * q * k  -> smem (tf32)
//   Phase B: adj_out = attn @ We^T + be   -> gmem
//   Phase C: colwise softmax over n, node = sum a*v, node_out = node@Wn^T+bn
// Smem layout (floats): sW 16384 | sAttn 32768 | sAdj 8192 | sQ 128 | sBa 128 | sNode 128
// XOR swizzle: idx(row,col) = row*128 + (col ^ ((row&7)<<2))
// ---------------------------------------------------------------------------
#define SMEM_FLOATS (16384 + 32768 + 8192 + 128 * 3)
#define SMEM_BYTES (SMEM_FLOATS * 4)

__global__ __launch_bounds__(256, 1) void fused_kernel(
    const float* __restrict__ mol_adj,
    const float* __restrict__ Wa, const float* __restrict__ ba,
    const float* __restrict__ We, const float* __restrict__ be,
    const float* __restrict__ Wn, const float* __restrict__ bn,
    float* __restrict__ out_node, float* __restrict__ out_adj) {
    extern __shared__ float sm[];
    float* sW = sm;                 // 16384
    float* sAttn = sm + 16384;      // 32768
    float* sAdj = sm + 49152;       // 8192 (reused as Phase C partial scratch)
    float* sQ = sm + 57344;         // 128
    float* sBa = sm + 57472;        // 128
    float* sNode = sm + 57600;      // 128

    const int bid = blockIdx.x;
    const int b = bid >> 8;
    const int t = threadIdx.x;
    const int wid = t >> 5;
    const int lane = t & 31;
    const int g = lane >> 2;   // group id (row within fragment)
    const int tg = lane & 3;   // thread in group

    // ---- load Wa -> sW (tf32-rounded, swizzled) ----
    {
        const float4* W4 = reinterpret_cast<const float4*>(Wa);
#pragma unroll
        for (int p = 0; p < 16; p++) {
            const int fidx = p * 256 + t;
            const int row = fidx >> 5;
            const int col4 = (fidx & 31) << 2;
            const float4 w = __ldg(W4 + fidx);
            float4 o;
            o.x = f2tf_f(w.x); o.y = f2tf_f(w.y); o.z = f2tf_f(w.z); o.w = f2tf_f(w.w);
            *reinterpret_cast<float4*>(&sW[row * CC + (col4 ^ ((row & 7) << 2))]) = o;
        }
    }
    if (t < CC) {
        sQ[t] = g_q[bid * CC + t];
        sBa[t] = __ldg(ba + t);
    }

    const float4* adj4 =
        reinterpret_cast<const float4*>(mol_adj + (size_t)bid * (MM * CC));
    float4 pf[8];
#pragma unroll
    for (int p = 0; p < 8; p++) pf[p] = __ldg(adj4 + p * 256 + t);

    __syncthreads();

    const float* gk = g_k + b * (MM * CC);

    // ==================== Phase A ====================
    for (int ci = 0; ci < 4; ci++) {
        // store prefetched chunk (64 rows) into sAdj, tf32-rounded + swizzled
#pragma unroll
        for (int p = 0; p < 8; p++) {
            const int fidx = p * 256 + t;
            const int row = fidx >> 5;
            const int col4 = (fidx & 31) << 2;
            const float4 w = pf[p];
            float4 o;
            o.x = f2tf_f(w.x); o.y = f2tf_f(w.y); o.z = f2tf_f(w.z); o.w = f2tf_f(w.w);
            *reinterpret_cast<float4*>(&sAdj[row * CC + (col4 ^ ((row & 7) << 2))]) = o;
        }
        __syncthreads();
        if (ci < 3) {
#pragma unroll
            for (int p = 0; p < 8; p++)
                pf[p] = __ldg(adj4 + (ci + 1) * 2048 + p * 256 + t);
        }

        const int mt = wid >> 1;       // 0..3 : 16-row tile in chunk
        const int nh = wid & 1;        // 0..1 : 64-col half
        const int lr = mt * 16;
        const int cb = nh * 64;

        float acc[8][4];
#pragma unroll
        for (int i = 0; i < 8; i++)
#pragma unroll
            for (int j = 0; j < 4; j++) acc[i][j] = 0.f;

        const int ra0 = (lr + g) * CC;
        const int ra1 = (lr + g + 8) * CC;
        const int swz = g << 2;  // (row&7)<<2 for all fragment rows used here

#pragma unroll
        for (int ks = 0; ks < 16; ks++) {
            const int k0 = ks * 8;
            const unsigned a0 = __float_as_uint(sAdj[ra0 + ((k0 + tg) ^ swz)]);
            const unsigned a1 = __float_as_uint(sAdj[ra1 + ((k0 + tg) ^ swz)]);
            const unsigned a2 = __float_as_uint(sAdj[ra0 + ((k0 + tg + 4) ^ swz)]);
            const unsigned a3 = __float_as_uint(sAdj[ra1 + ((k0 + tg + 4) ^ swz)]);
#pragma unroll
            for (int nt = 0; nt < 8; nt++) {
                const int rb_ = (cb + nt * 8 + g) * CC;
                const unsigned b0 = __float_as_uint(sW[rb_ + ((k0 + tg) ^ swz)]);
                const unsigned b1 = __float_as_uint(sW[rb_ + ((k0 + tg + 4) ^ swz)]);
                mma_tf32(acc[nt], a0, a1, a2, a3, b0, b1);
            }
        }

        // epilogue: attn = (E + ba) * q * k  -> sAttn (tf32)
#pragma unroll
        for (int nt = 0; nt < 8; nt++) {
            const int col = cb + nt * 8 + tg * 2;
            const float q0 = sQ[col], q1 = sQ[col + 1];
            const float ba0 = sBa[col], ba1 = sBa[col + 1];
            const int n0 = ci * 64 + lr + g;
            const int n1 = n0 + 8;
            const float2 kk0 =
                __ldg(reinterpret_cast<const float2*>(gk + n0 * CC + col));
            const float2 kk1 =
                __ldg(reinterpret_cast<const float2*>(gk + n1 * CC + col));
            float2 s0, s1;
            s0.x = f2tf_f((acc[nt][0] + ba0) * q0 * kk0.x);
            s0.y = f2tf_f((acc[nt][1] + ba1) * q1 * kk0.y);
            s1.x = f2tf_f((acc[nt][2] + ba0) * q0 * kk1.x);
            s1.y = f2tf_f((acc[nt][3] + ba1) * q1 * kk1.y);
            *reinterpret_cast<float2*>(&sAttn[n0 * CC + (col ^ ((n0 & 7) << 2))]) = s0;
            *reinterpret_cast<float2*>(&sAttn[n1 * CC + (col ^ ((n1 & 7) << 2))]) = s1;
        }
        __syncthreads();
    }

    // ---- load We -> sW (overwrite Wa) ----
    {
        const float4* W4 = reinterpret_cast<const float4*>(We);
#pragma unroll
        for (int p = 0; p < 16; p++) {
            const int fidx = p * 256 + t;
            const int row = fidx >> 5;
            const int col4 = (fidx & 31) << 2;
            const float4 w = __ldg(W4 + fidx);
            float4 o;
            o.x = f2tf_f(w.x); o.y = f2tf_f(w.y); o.z = f2tf_f(w.z); o.w = f2tf_f(w.w);
            *reinterpret_cast<float4*>(&sW[row * CC + (col4 ^ ((row & 7) << 2))]) = o;
        }
    }
    __syncthreads();

    // ==================== Phase B: adj_out = attn @ We^T + be ====================
    float* oadj = out_adj + (size_t)bid * (MM * CC);
#pragma unroll 1
    for (int tt = 0; tt < 4; tt++) {
        const int rb = wid * 32 + (tt >> 1) * 16;
        const int cb = (tt & 1) * 64;

        float acc[8][4];
#pragma unroll
        for (int i = 0; i < 8; i++)
#pragma unroll
            for (int j = 0; j < 4; j++) acc[i][j] = 0.f;

        const int ra0 = (rb + g) * CC;
        const int ra1 = (rb + g + 8) * CC;
        const int swz = g << 2;

#pragma unroll
        for (int ks = 0; ks < 16; ks++) {
            const int k0 = ks * 8;
            const unsigned a0 = __float_as_uint(sAttn[ra0 + ((k0 + tg) ^ swz)]);
            const unsigned a1 = __float_as_uint(sAttn[ra1 + ((k0 + tg) ^ swz)]);
            const unsigned a2 = __float_as_uint(sAttn[ra0 + ((k0 + tg + 4) ^ swz)]);
            const unsigned a3 = __float_as_uint(sAttn[ra1 + ((k0 + tg + 4) ^ swz)]);
#pragma unroll
            for (int nt = 0; nt < 8; nt++) {
                const int rb_ = (cb + nt * 8 + g) * CC;
                const unsigned b0 = __float_as_uint(sW[rb_ + ((k0 + tg) ^ swz)]);
                const unsigned b1 = __float_as_uint(sW[rb_ + ((k0 + tg + 4) ^ swz)]);
                mma_tf32(acc[nt], a0, a1, a2, a3, b0, b1);
            }
        }

#pragma unroll
        for (int nt = 0; nt < 8; nt++) {
            const int col = cb + nt * 8 + tg * 2;
            const float be0 = __ldg(be + col), be1 = __ldg(be + col + 1);
            const int n0 = rb + g;
            const int n1 = n0 + 8;
            float2 o0, o1;
            o0.x = acc[nt][0] + be0; o0.y = acc[nt][1] + be1;
            o1.x = acc[nt][2] + be0; o1.y = acc[nt][3] + be1;
            *reinterpret_cast<float2*>(oadj + (size_t)n0 * CC + col) = o0;
            *reinterpret_cast<float2*>(oadj + (size_t)n1 * CC + col) = o1;
        }
    }

    // ==================== Phase C: softmax over n + node branch ====================
    // All 256 threads: thread t handles column (t&127), n-half (t>>7).
    // Partials go into sAdj scratch: [half*384 + {0,128,256} + c]
    {
        const int c = t & 127;
        const int half = t >> 7;
        const int nbeg = half * 128;
        float mx = -3.0e38f;
#pragma unroll 4
        for (int n = nbeg; n < nbeg + 128; n++)
            mx = fmaxf(mx, sAttn[n * CC + (c ^ ((n & 7) << 2))]);

        float s = 0.f, nv = 0.f;
        const float* gv = g_v + b * (MM * CC);
#pragma unroll 4
        for (int n = nbeg; n < nbeg + 128; n++) {
            const float e = __expf(sAttn[n * CC + (c ^ ((n & 7) << 2))] - mx);
            s += e;
            nv += e * __ldg(gv + n * CC + c);
        }
        sAdj[half * 384 + c] = mx;
        sAdj[half * 384 + 128 + c] = s;
        sAdj[half * 384 + 256 + c] = nv;
    }
    __syncthreads();
    if (t < CC) {
        const float m0 = sAdj[t], m1 = sAdj[384 + t];
        const float M = fmaxf(m0, m1);
        const float w0 = __expf(m0 - M), w1 = __expf(m1 - M);
        const float s = sAdj[128 + t] * w0 + sAdj[384 + 128 + t] * w1;
        const float nv = sAdj[256 + t] * w0 + sAdj[384 + 256 + t] * w1;
        sNode[t] = nv / s;
    }
    __syncthreads();
    if (t < CC) {
        float accn = __ldg(bn + t);
        const float4* wn4 = reinterpret_cast<const float4*>(Wn + t * CC);
#pragma unroll 8
        for (int j4 = 0; j4 < 32; j4++) {
            const float4 w = __ldg(wn4 + j4);
            const float4 x = *reinterpret_cast<const float4*>(&sNode[j4 * 4]);
            accn += x.x * w.x + x.y * w.y + x.z * w.z + x.w * w.w;
        }
        out_node[bid * CC + t] = accn;
    }
}

// ---------------------------------------------------------------------------
extern "C" void kernel_launch(void* const* d_in, const int* in_sizes, int n_in,
                              void* d_out, int out_size) {
    const float* annot = (const float*)d_in[0];
    const float* adj   = (const float*)d_in[1];
    const float* prot  = (const float*)d_in[2];
    const float* Wq = (const float*)d_in[3];  const float* bq = (const float*)d_in[4];
    const float* Wk = (const float*)d_in[5];  const float* bk = (const float*)d_in[6];
    const float* Wv = (const float*)d_in[7];  const float* bv = (const float*)d_in[8];
    const float* Wa = (const float*)d_in[9];  const float* ba = (const float*)d_in[10];
    const float* Wn = (const float*)d_in[11]; const float* bn = (const float*)d_in[12];
    const float* We = (const float*)d_in[13]; const float* be = (const float*)d_in[14];

    float* out_node = (float*)d_out;                    // [8,256,128]
    float* out_adj = (float*)d_out + BB * MM * CC;      // [8,256,256,128]

    cudaFuncSetAttribute(fused_kernel, cudaFuncAttributeMaxDynamicSharedMemorySize,
                         SMEM_BYTES);

    qkv_kernel<<<BB * MM / 8, 128>>>(annot, prot, Wq, bq, Wk, bk, Wv, bv);
    fused_kernel<<<BB * MM, 256, SMEM_BYTES>>>(adj, Wa, ba, We, be, Wn, bn,
                                               out_node, out_adj);
}

// round 4
// speedup vs baseline: 1.0642x; 1.0642x over previous
#include <cuda_runtime.h>
#include <cstdint>
#include <cstddef>

#define BB 8
#define MM 256
#define CC 128
#define QK_SCALE 0.08838834764831843f  // 1/sqrt(128)

// scratch for q (pre-scaled), k, v : 1 MB each
__device__ float g_q[BB * MM * CC];
__device__ float g_k[BB * MM * CC];
__device__ float g_v[BB * MM * CC];

__device__ __forceinline__ unsigned f2tf(float x) {
    unsigned r;
    asm("cvt.rna.tf32.f32 %0, %1;" : "=r"(r) : "f"(x));
    return r;
}
__device__ __forceinline__ float f2tf_f(float x) { return __uint_as_float(f2tf(x)); }

__device__ __forceinline__ void mma_tf32(float c[4], unsigned a0, unsigned a1,
                                         unsigned a2, unsigned a3,
                                         unsigned b0, unsigned b1) {
    asm volatile(
        "mma.sync.aligned.m16n8k8.row.col.f32.tf32.tf32.f32 "
        "{%0,%1,%2,%3},{%4,%5,%6,%7},{%8,%9},{%0,%1,%2,%3};"
        : "+f"(c[0]), "+f"(c[1]), "+f"(c[2]), "+f"(c[3])
        : "r"(a0), "r"(a1), "r"(a2), "r"(a3), "r"(b0), "r"(b1));
}

// ---------------------------------------------------------------------------
// q/k/v pre-kernel: 256 blocks x 128 threads, 8 rows per block.
// ---------------------------------------------------------------------------
__global__ __launch_bounds__(128) void qkv_kernel(
    const float* __restrict__ annot, const float* __restrict__ prot,
    const float* __restrict__ Wq, const float* __restrict__ bq,
    const float* __restrict__ Wk, const float* __restrict__ bk,
    const float* __restrict__ Wv, const float* __restrict__ bv) {
    __shared__ float sa[8][CC];
    __shared__ float sp[8][CC];
    const int r0 = blockIdx.x * 8;
    const int t = threadIdx.x;

#pragma unroll
    for (int rr = 0; rr < 8; rr++) {
        sa[rr][t] = annot[(r0 + rr) * CC + t];
        sp[rr][t] = prot[(r0 + rr) * CC + t];
    }
    __syncthreads();

    float aq[8], ak[8], av[8];
#pragma unroll
    for (int rr = 0; rr < 8; rr++) { aq[rr] = 0.f; ak[rr] = 0.f; av[rr] = 0.f; }

    const float4* wq4 = reinterpret_cast<const float4*>(Wq + t * CC);
    const float4* wk4 = reinterpret_cast<const float4*>(Wk + t * CC);
    const float4* wv4 = reinterpret_cast<const float4*>(Wv + t * CC);

#pragma unroll 8
    for (int j4 = 0; j4 < 32; j4++) {
        const float4 wq = __ldg(wq4 + j4);
        const float4 wk = __ldg(wk4 + j4);
        const float4 wv = __ldg(wv4 + j4);
#pragma unroll
        for (int rr = 0; rr < 8; rr++) {
            const float4 xa = *reinterpret_cast<const float4*>(&sa[rr][j4 * 4]);
            const float4 xp = *reinterpret_cast<const float4*>(&sp[rr][j4 * 4]);
            aq[rr] += xa.x * wq.x + xa.y * wq.y + xa.z * wq.z + xa.w * wq.w;
            ak[rr] += xp.x * wk.x + xp.y * wk.y + xp.z * wk.z + xp.w * wk.w;
            av[rr] += xa.x * wv.x + xa.y * wv.y + xa.z * wv.z + xa.w * wv.w;
        }
    }

    const float bqv = __ldg(bq + t), bkv = __ldg(bk + t), bvv = __ldg(bv + t);
#pragma unroll
    for (int rr = 0; rr < 8; rr++) {
        const int o = (r0 + rr) * CC + t;
        g_q[o] = (aq[rr] + bqv) * QK_SCALE;
        g_k[o] = ak[rr] + bkv;
        g_v[o] = av[rr] + bvv;
    }
}

// ---------------------------------------------------------------------------
// Fused main kernel: one CTA per (b, m), 512 threads (16 warps).
//   Phase A: E = mol_adj[b,m] @ Wa^T + ba ; attn = E * q * k  -> smem (tf32)
//   Phase B: adj_out = attn @ We^T + be   -> gmem
//   Phase C: colwise softmax over n, node = sum a*v, node_out = node@Wn^T+bn
// Smem layout (floats): sW 16384 | sAttn 32768 | sAdj 8192 | sQ 128 | sBa 128 | sNode 128
// XOR swizzle: idx(row,col) = row*128 + (col ^ ((row&7)<<2))
// ---------------------------------------------------------------------------
#define NT 512
#define SMEM_FLOATS (16384 + 32768 + 8192 + 128 * 3)
#define SMEM_BYTES (SMEM_FLOATS * 4)

__global__ __launch_bounds__(NT, 1) void fused_kernel(
    const float* __restrict__ mol_adj,
    const float* __restrict__ Wa, const float* __restrict__ ba,
    const float* __restrict__ We, const float* __restrict__ be,
    const float* __restrict__ Wn, const float* __restrict__ bn,
    float* __restrict__ out_node, float* __restrict__ out_adj) {
    extern __shared__ float sm[];
    float* sW = sm;                 // 16384
    float* sAttn = sm + 16384;      // 32768
    float* sAdj = sm + 49152;       // 8192 (reused as Phase C partial scratch)
    float* sQ = sm + 57344;         // 128
    float* sBa = sm + 57472;        // 128
    float* sNode = sm + 57600;      // 128

    const int bid = blockIdx.x;
    const int b = bid >> 8;
    const int t = threadIdx.x;
    const int wid = t >> 5;
    const int lane = t & 31;
    const int g = lane >> 2;   // fragment row group
    const int tg = lane & 3;   // thread in group

    // ---- load Wa -> sW (tf32-rounded, swizzled) ----
    {
        const float4* W4 = reinterpret_cast<const float4*>(Wa);
#pragma unroll
        for (int p = 0; p < 8; p++) {
            const int fidx = p * NT + t;
            const int row = fidx >> 5;
            const int col4 = (fidx & 31) << 2;
            const float4 w = __ldg(W4 + fidx);
            float4 o;
            o.x = f2tf_f(w.x); o.y = f2tf_f(w.y); o.z = f2tf_f(w.z); o.w = f2tf_f(w.w);
            *reinterpret_cast<float4*>(&sW[row * CC + (col4 ^ ((row & 7) << 2))]) = o;
        }
    }
    if (t < CC) {
        sQ[t] = g_q[bid * CC + t];
        sBa[t] = __ldg(ba + t);
    }

    const float4* adj4 =
        reinterpret_cast<const float4*>(mol_adj + (size_t)bid * (MM * CC));
    float4 pf[4];
#pragma unroll
    for (int p = 0; p < 4; p++) pf[p] = __ldg(adj4 + p * NT + t);

    __syncthreads();

    const float* gk = g_k + b * (MM * CC);

    // ==================== Phase A ====================
    for (int ci = 0; ci < 4; ci++) {
        // store prefetched chunk (64 rows) into sAdj, tf32-rounded + swizzled
#pragma unroll
        for (int p = 0; p < 4; p++) {
            const int fidx = p * NT + t;
            const int row = fidx >> 5;
            const int col4 = (fidx & 31) << 2;
            const float4 w = pf[p];
            float4 o;
            o.x = f2tf_f(w.x); o.y = f2tf_f(w.y); o.z = f2tf_f(w.z); o.w = f2tf_f(w.w);
            *reinterpret_cast<float4*>(&sAdj[row * CC + (col4 ^ ((row & 7) << 2))]) = o;
        }
        __syncthreads();
        if (ci < 3) {
#pragma unroll
            for (int p = 0; p < 4; p++)
                pf[p] = __ldg(adj4 + (ci + 1) * 2048 + p * NT + t);
        }

        const int mt = wid & 3;    // 0..3 : 16-row tile in chunk
        const int nq = wid >> 2;   // 0..3 : 32-col quarter
        const int lr = mt * 16;
        const int cb = nq * 32;

        float acc[4][4];
#pragma unroll
        for (int i = 0; i < 4; i++)
#pragma unroll
            for (int j = 0; j < 4; j++) acc[i][j] = 0.f;

        const int ra0 = (lr + g) * CC;
        const int ra1 = (lr + g + 8) * CC;
        const int swz = g << 2;

#pragma unroll
        for (int ks = 0; ks < 16; ks++) {
            const int k0 = ks * 8;
            const unsigned a0 = __float_as_uint(sAdj[ra0 + ((k0 + tg) ^ swz)]);
            const unsigned a1 = __float_as_uint(sAdj[ra1 + ((k0 + tg) ^ swz)]);
            const unsigned a2 = __float_as_uint(sAdj[ra0 + ((k0 + tg + 4) ^ swz)]);
            const unsigned a3 = __float_as_uint(sAdj[ra1 + ((k0 + tg + 4) ^ swz)]);
#pragma unroll
            for (int nt = 0; nt < 4; nt++) {
                const int rb_ = (cb + nt * 8 + g) * CC;
                const unsigned b0 = __float_as_uint(sW[rb_ + ((k0 + tg) ^ swz)]);
                const unsigned b1 = __float_as_uint(sW[rb_ + ((k0 + tg + 4) ^ swz)]);
                mma_tf32(acc[nt], a0, a1, a2, a3, b0, b1);
            }
        }

        // epilogue: attn = (E + ba) * q * k  -> sAttn (tf32)
#pragma unroll
        for (int nt = 0; nt < 4; nt++) {
            const int col = cb + nt * 8 + tg * 2;
            const float q0 = sQ[col], q1 = sQ[col + 1];
            const float ba0 = sBa[col], ba1 = sBa[col + 1];
            const int n0 = ci * 64 + lr + g;
            const int n1 = n0 + 8;
            const float2 kk0 =
                __ldg(reinterpret_cast<const float2*>(gk + n0 * CC + col));
            const float2 kk1 =
                __ldg(reinterpret_cast<const float2*>(gk + n1 * CC + col));
            float2 s0, s1;
            s0.x = f2tf_f((acc[nt][0] + ba0) * q0 * kk0.x);
            s0.y = f2tf_f((acc[nt][1] + ba1) * q1 * kk0.y);
            s1.x = f2tf_f((acc[nt][2] + ba0) * q0 * kk1.x);
            s1.y = f2tf_f((acc[nt][3] + ba1) * q1 * kk1.y);
            *reinterpret_cast<float2*>(&sAttn[n0 * CC + (col ^ ((n0 & 7) << 2))]) = s0;
            *reinterpret_cast<float2*>(&sAttn[n1 * CC + (col ^ ((n1 & 7) << 2))]) = s1;
        }
        __syncthreads();
    }

    // ---- load We -> sW (overwrite Wa) ----
    {
        const float4* W4 = reinterpret_cast<const float4*>(We);
#pragma unroll
        for (int p = 0; p < 8; p++) {
            const int fidx = p * NT + t;
            const int row = fidx >> 5;
            const int col4 = (fidx & 31) << 2;
            const float4 w = __ldg(W4 + fidx);
            float4 o;
            o.x = f2tf_f(w.x); o.y = f2tf_f(w.y); o.z = f2tf_f(w.z); o.w = f2tf_f(w.w);
            *reinterpret_cast<float4*>(&sW[row * CC + (col4 ^ ((row & 7) << 2))]) = o;
        }
    }
    __syncthreads();

    // ==================== Phase B: adj_out = attn @ We^T + be ====================
    float* oadj = out_adj + (size_t)bid * (MM * CC);
    // per-thread bias values for both column halves (hoisted out of tt loop)
    float beh[2][8][2];
#pragma unroll
    for (int tt = 0; tt < 2; tt++)
#pragma unroll
        for (int nt = 0; nt < 8; nt++) {
            const int col = tt * 64 + nt * 8 + tg * 2;
            beh[tt][nt][0] = __ldg(be + col);
            beh[tt][nt][1] = __ldg(be + col + 1);
        }

#pragma unroll 1
    for (int tt = 0; tt < 2; tt++) {
        const int rb = wid * 16;      // 16 warps x 16 rows = 256 rows
        const int cb = tt * 64;

        float acc[8][4];
#pragma unroll
        for (int i = 0; i < 8; i++)
#pragma unroll
            for (int j = 0; j < 4; j++) acc[i][j] = 0.f;

        const int ra0 = (rb + g) * CC;
        const int ra1 = (rb + g + 8) * CC;
        const int swz = g << 2;

#pragma unroll
        for (int ks = 0; ks < 16; ks++) {
            const int k0 = ks * 8;
            const unsigned a0 = __float_as_uint(sAttn[ra0 + ((k0 + tg) ^ swz)]);
            const unsigned a1 = __float_as_uint(sAttn[ra1 + ((k0 + tg) ^ swz)]);
            const unsigned a2 = __float_as_uint(sAttn[ra0 + ((k0 + tg + 4) ^ swz)]);
            const unsigned a3 = __float_as_uint(sAttn[ra1 + ((k0 + tg + 4) ^ swz)]);
#pragma unroll
            for (int nt = 0; nt < 8; nt++) {
                const int rb_ = (cb + nt * 8 + g) * CC;
                const unsigned b0 = __float_as_uint(sW[rb_ + ((k0 + tg) ^ swz)]);
                const unsigned b1 = __float_as_uint(sW[rb_ + ((k0 + tg + 4) ^ swz)]);
                mma_tf32(acc[nt], a0, a1, a2, a3, b0, b1);
            }
        }

#pragma unroll
        for (int nt = 0; nt < 8; nt++) {
            const int col = cb + nt * 8 + tg * 2;
            const int n0 = rb + g;
            const int n1 = n0 + 8;
            float2 o0, o1;
            o0.x = acc[nt][0] + beh[tt][nt][0]; o0.y = acc[nt][1] + beh[tt][nt][1];
            o1.x = acc[nt][2] + beh[tt][nt][0]; o1.y = acc[nt][3] + beh[tt][nt][1];
            *reinterpret_cast<float2*>(oadj + (size_t)n0 * CC + col) = o0;
            *reinterpret_cast<float2*>(oadj + (size_t)n1 * CC + col) = o1;
        }
    }

    // ==================== Phase C: softmax over n + node branch ====================
    // 512 threads: thread t handles column (t&127), n-quarter (t>>7) of 64 rows.
    {
        const int c = t & 127;
        const int qtr = t >> 7;
        const int nbeg = qtr * 64;
        float mx = -3.0e38f;
#pragma unroll 4
        for (int n = nbeg; n < nbeg + 64; n++)
            mx = fmaxf(mx, sAttn[n * CC + (c ^ ((n & 7) << 2))]);

        float s = 0.f, nv = 0.f;
        const float* gv = g_v + b * (MM * CC);
#pragma unroll 4
        for (int n = nbeg; n < nbeg + 64; n++) {
            const float e = __expf(sAttn[n * CC + (c ^ ((n & 7) << 2))] - mx);
            s += e;
            nv += e * __ldg(gv + n * CC + c);
        }
        sAdj[qtr * 384 + c] = mx;
        sAdj[qtr * 384 + 128 + c] = s;
        sAdj[qtr * 384 + 256 + c] = nv;
    }
    __syncthreads();
    if (t < CC) {
        float M = sAdj[t];
#pragma unroll
        for (int q = 1; q < 4; q++) M = fmaxf(M, sAdj[q * 384 + t]);
        float s = 0.f, nv = 0.f;
#pragma unroll
        for (int q = 0; q < 4; q++) {
            const float w = __expf(sAdj[q * 384 + t] - M);
            s += sAdj[q * 384 + 128 + t] * w;
            nv += sAdj[q * 384 + 256 + t] * w;
        }
        sNode[t] = nv / s;
    }
    __syncthreads();
    if (t < CC) {
        float accn = __ldg(bn + t);
        const float4* wn4 = reinterpret_cast<const float4*>(Wn + t * CC);
#pragma unroll 8
        for (int j4 = 0; j4 < 32; j4++) {
            const float4 w = __ldg(wn4 + j4);
            const float4 x = *reinterpret_cast<const float4*>(&sNode[j4 * 4]);
            accn += x.x * w.x + x.y * w.y + x.z * w.z + x.w * w.w;
        }
        out_node[bid * CC + t] = accn;
    }
}

// ---------------------------------------------------------------------------
extern "C" void kernel_launch(void* const* d_in, const int* in_sizes, int n_in,
                              void* d_out, int out_size) {
    const float* annot = (const float*)d_in[0];
    const float* adj   = (const float*)d_in[1];
    const float* prot  = (const float*)d_in[2];
    const float* Wq = (const float*)d_in[3];  const float* bq = (const float*)d_in[4];
    const float* Wk = (const float*)d_in[5];  const float* bk = (const float*)d_in[6];
    const float* Wv = (const float*)d_in[7];  const float* bv = (const float*)d_in[8];
    const float* Wa = (const float*)d_in[9];  const float* ba = (const float*)d_in[10];
    const float* Wn = (const float*)d_in[11]; const float* bn = (const float*)d_in[12];
    const float* We = (const float*)d_in[13]; const float* be = (const float*)d_in[14];

    float* out_node = (float*)d_out;                    // [8,256,128]
    float* out_adj = (float*)d_out + BB * MM * CC;      // [8,256,256,128]

    cudaFuncSetAttribute(fused_kernel, cudaFuncAttributeMaxDynamicSharedMemorySize,
                         SMEM_BYTES);

    qkv_kernel<<<BB * MM / 8, 128>>>(annot, prot, Wq, bq, Wk, bk, Wv, bv);
    fused_kernel<<<BB * MM, NT, SMEM_BYTES>>>(adj, Wa, ba, We, be, Wn, bn,
                                              out_node, out_adj);
}